// round 11
// baseline (speedup 1.0000x reference)
#include <cuda_runtime.h>
#include <cuda_fp16.h>
#include <cuda_fp8.h>
#include <cstdint>

// ---------------------------------------------------------------------------
// PSAttention (B=32, CIN=2048, COUT=HW=1024)
//   GEMM1 (Y1 = Wr@X + br)          : fp16 mma.sync m16n8k16 (precision-critical)
//   GEMM2/3 (logits)                : fp8 e4m3 mma.sync m16n8k32 (2x rate)
//   GEMM4 (out = Y1 + C@D^T)        : fp8 e4m3
// Scales: Wc/Wd x16, Y1 x2 (logits /32); softmax x256 (GEMM4 /65536).
// ---------------------------------------------------------------------------

#define NB 32
#define ELEMS (1024 * 1024)

__device__ float          g_Y1 [NB * ELEMS];           // fp32 Y1
__device__ float          g_C  [NB * ELEMS];           // logits C (fp32)
__device__ float          g_D  [NB * ELEMS];           // logits D (fp32)
__device__ __half         g_XT [NB * 1024 * 2048];     // X^T fp16 (B for GEMM1)
__device__ unsigned char  g_Y1s8 [NB * ELEMS];         // Y1 fp8 x2, [c][n]
__device__ unsigned char  g_Y1s8T[NB * ELEMS];         // Y1^T fp8 x2, [n][c]
__device__ unsigned char  g_Ch8[NB * ELEMS];           // softmax C fp8 x256
__device__ unsigned char  g_Dh8[NB * ELEMS];           // softmax D fp8 x256
__device__ __half         g_Wr [1024 * 2048];
__device__ unsigned char  g_Wc8[1024 * 1024];          // Wc fp8 x16
__device__ unsigned char  g_Wd8[1024 * 1024];          // Wd fp8 x16

// ---------------------------------------------------------------------------
// helpers
// ---------------------------------------------------------------------------
__device__ __forceinline__ uint32_t smem_u32(const void* p) {
    uint32_t a;
    asm("{ .reg .u64 t; cvta.to.shared.u64 t, %1; cvt.u32.u64 %0, t; }" : "=r"(a) : "l"(p));
    return a;
}
#define CP16(dst, src) \
    asm volatile("cp.async.cg.shared.global [%0], [%1], 16;" :: "r"(dst), "l"(src))

__device__ __forceinline__ uint32_t swz(uint32_t off) {
    return off ^ ((off >> 3) & 0x70);
}
__device__ __forceinline__ void ldsm4(uint32_t* r, uint32_t a) {
    asm volatile("ldmatrix.sync.aligned.m8n8.x4.shared.b16 {%0,%1,%2,%3}, [%4];"
        : "=r"(r[0]), "=r"(r[1]), "=r"(r[2]), "=r"(r[3]) : "r"(a));
}
__device__ __forceinline__ void mma_f16(float* c, const uint32_t* a, const uint32_t* b) {
    asm volatile("mma.sync.aligned.m16n8k16.row.col.f32.f16.f16.f32 "
        "{%0,%1,%2,%3},{%4,%5,%6,%7},{%8,%9},{%0,%1,%2,%3};"
        : "+f"(c[0]), "+f"(c[1]), "+f"(c[2]), "+f"(c[3])
        : "r"(a[0]), "r"(a[1]), "r"(a[2]), "r"(a[3]), "r"(b[0]), "r"(b[1]));
}
__device__ __forceinline__ void mma_f8(float* c, const uint32_t* a, const uint32_t* b) {
    asm volatile("mma.sync.aligned.m16n8k32.row.col.f32.e4m3.e4m3.f32 "
        "{%0,%1,%2,%3},{%4,%5,%6,%7},{%8,%9},{%0,%1,%2,%3};"
        : "+f"(c[0]), "+f"(c[1]), "+f"(c[2]), "+f"(c[3])
        : "r"(a[0]), "r"(a[1]), "r"(a[2]), "r"(a[3]), "r"(b[0]), "r"(b[1]));
}
__device__ __forceinline__ unsigned short fp8x2(float x, float y) {
    return (unsigned short)__nv_cvt_float2_to_fp8x2(make_float2(x, y),
                                                    __NV_SATFINITE, __NV_E4M3);
}

// ---------------------------------------------------------------------------
// stage loader (byte-addressed; identical geometry for fp16 and fp8):
// A[128 rows x 128B] @ +0, B[256 rows x 128B] @ +16384. Stage = 48KB.
// ---------------------------------------------------------------------------
#define STAGE 49152u
__device__ __forceinline__ void load_stage(
    uint32_t sb, int s, long aRowB0, long bRowB0, int KB, int ksB,
    const char* A, const char* B, int tid)
{
    uint32_t buf = sb + (uint32_t)(s % 3) * STAGE;
#pragma unroll
    for (int i = 0; i < 4; i++) {          // A: 128 rows x 8 x 16B
        int idx = tid + (i << 8);
        int r = idx >> 3, c = idx & 7;
        uint32_t sw = swz((uint32_t)(r * 128 + c * 16));
        CP16(buf + sw, A + aRowB0 + (long)r * KB + ksB + (c << 4));
    }
#pragma unroll
    for (int i = 0; i < 8; i++) {          // B: 256 rows x 8 x 16B
        int idx = tid + (i << 8);
        int r = idx >> 3, c = idx & 7;
        uint32_t sw = swz((uint32_t)(r * 128 + c * 16));
        CP16(buf + 16384u + sw, B + bRowB0 + (long)r * KB + ksB + (c << 4));
    }
    asm volatile("cp.async.commit_group;" ::: "memory");
}

// ---------------------------------------------------------------------------
// GEMM: out[1024,1024] per batch = A[M,K] * B[N,K]^T, K-major operands.
// DT 0: fp16 (k16/step)   DT 1: fp8 e4m3 (k32/step) — same byte layout.
// MODE 0: +bias, write fp32 outF + fp8(out*2) natural layout
// MODE 1: acc*oscale + bias -> fp32 outF
// MODE 2: acc*oscale + addend -> fp32 outF
// CTA 128x256, 8 warps = 2(m) x 4(n), warp tile 64x64. 3-stage cp.async.
// ---------------------------------------------------------------------------
template<int DT, int MODE>
__global__ __launch_bounds__(256, 1)
void gemm_mma(const char* __restrict__ A_, long strideAB,
              const char* __restrict__ B_, long strideBB, int KB,
              const float* __restrict__ bias, float oscale,
              float* __restrict__ outF,
              const float* __restrict__ addend,
              unsigned char* __restrict__ out8)
{
    extern __shared__ char smraw[];
    uint32_t sb = (smem_u32(smraw) + 1023u) & ~1023u;
    const int tid = threadIdx.x, lane = tid & 31, wid = tid >> 5;
    const int bz = blockIdx.z;
    const int m0 = blockIdx.y * 128, n0 = blockIdx.x * 256;
    const int ES = (DT == 0) ? 2 : 1;

    const char* A = A_ + (long)bz * strideAB;
    const char* B = B_ + (long)bz * strideBB;
    const long aRowB0 = (long)m0 * KB;
    const long bRowB0 = (long)n0 * KB;

    const int wm0 = (wid & 1) * 64;
    const int wn0 = (wid >> 1) * 64;

    float acc[4][8][4];
#pragma unroll
    for (int a = 0; a < 4; a++)
#pragma unroll
        for (int b = 0; b < 8; b++)
#pragma unroll
            for (int c = 0; c < 4; c++) acc[a][b][c] = 0.0f;

    const int nC = KB >> 7;                 // stages of 128B along K
    load_stage(sb, 0, aRowB0, bRowB0, KB, 0,   A, B, tid);
    load_stage(sb, 1, aRowB0, bRowB0, KB, 128, A, B, tid);

    const int      arow = wm0 + (lane & 15);
    const uint32_t akb0 = (uint32_t)((lane >> 4) * 16);
    const int      brow = wn0 + (lane & 7) + ((lane >> 4) << 3);
    const uint32_t bkb0 = (uint32_t)(((lane >> 3) & 1) * 16);

    for (int s = 0; s < nC; s++) {
        if (s == nC - 1) asm volatile("cp.async.wait_group 0;" ::: "memory");
        else             asm volatile("cp.async.wait_group 1;" ::: "memory");
        __syncthreads();

        uint32_t aB = sb + (uint32_t)(s % 3) * STAGE;
        uint32_t bB = aB + 16384u;

#pragma unroll
        for (int ks = 0; ks < 4; ks++) {       // 32B of K per step
            uint32_t ah[4][4], bb[4][4];
            const uint32_t akb = (uint32_t)(ks * 32) + akb0;
            const uint32_t bkb = (uint32_t)(ks * 32) + bkb0;
#pragma unroll
            for (int mt = 0; mt < 4; mt++)
                ldsm4(ah[mt], aB + swz((uint32_t)((arow + mt * 16) * 128) + akb));
#pragma unroll
            for (int q = 0; q < 4; q++)
                ldsm4(bb[q], bB + swz((uint32_t)((brow + q * 16) * 128) + bkb));
#pragma unroll
            for (int mt = 0; mt < 4; mt++)
#pragma unroll
                for (int nb = 0; nb < 8; nb++) {
                    if (DT == 0) mma_f16(acc[mt][nb], ah[mt], &bb[nb >> 1][(nb & 1) * 2]);
                    else         mma_f8 (acc[mt][nb], ah[mt], &bb[nb >> 1][(nb & 1) * 2]);
                }
        }
        if (s + 2 < nC)
            load_stage(sb, s + 2, aRowB0, bRowB0, KB, (s + 2) << 7, A, B, tid);
    }

    // ---- epilogue ----------------------------------------------------------
    const long ob = (long)bz << 20;
#pragma unroll
    for (int mt = 0; mt < 4; mt++) {
        const int r0 = m0 + wm0 + mt * 16 + (lane >> 2);
        float b0 = 0.0f, b1 = 0.0f;
        if (MODE == 0 || MODE == 1) { b0 = __ldg(&bias[r0]); b1 = __ldg(&bias[r0 + 8]); }
#pragma unroll
        for (int nb = 0; nb < 8; nb++) {
            const int col = n0 + wn0 + nb * 8 + (lane & 3) * 2;
            float v0, v1, v2, v3;
            if (MODE == 0) {
                v0 = acc[mt][nb][0] + b0; v1 = acc[mt][nb][1] + b0;
                v2 = acc[mt][nb][2] + b1; v3 = acc[mt][nb][3] + b1;
            } else if (MODE == 1) {
                v0 = acc[mt][nb][0] * oscale + b0; v1 = acc[mt][nb][1] * oscale + b0;
                v2 = acc[mt][nb][2] * oscale + b1; v3 = acc[mt][nb][3] * oscale + b1;
            } else {
                v0 = acc[mt][nb][0] * oscale; v1 = acc[mt][nb][1] * oscale;
                v2 = acc[mt][nb][2] * oscale; v3 = acc[mt][nb][3] * oscale;
            }
            const long i0 = ob + (long)r0 * 1024 + col;
            const long i1 = ob + (long)(r0 + 8) * 1024 + col;
            if (MODE == 2) {
                float2 a0 = *(const float2*)(addend + i0);
                float2 a1 = *(const float2*)(addend + i1);
                v0 += a0.x; v1 += a0.y; v2 += a1.x; v3 += a1.y;
            }
            *(float2*)(outF + i0) = make_float2(v0, v1);
            *(float2*)(outF + i1) = make_float2(v2, v3);
            if (MODE == 0) {
                *(unsigned short*)(out8 + i0) = fp8x2(v0 * 2.0f, v1 * 2.0f);
                *(unsigned short*)(out8 + i1) = fp8x2(v2 * 2.0f, v3 * 2.0f);
            }
        }
    }
}

// ---------------------------------------------------------------------------
// conversions
// ---------------------------------------------------------------------------
__global__ void conv_x_T(const float* __restrict__ X, __half* __restrict__ o)
{
    __shared__ float tile[32][33];
    const int b = blockIdx.z;
    const int c0 = blockIdx.y * 32, n0 = blockIdx.x * 32;
    const int tx = threadIdx.x, ty = threadIdx.y;       // (32, 8)
    const float* src = X + ((long)b * 2048 + c0) * 1024 + n0;
#pragma unroll
    for (int i = 0; i < 4; i++)
        tile[ty + 8 * i][tx] = src[(long)(ty + 8 * i) * 1024 + tx];
    __syncthreads();
    const long obase = ((long)b * 1024 + n0) * 2048 + c0;
#pragma unroll
    for (int i = 0; i < 4; i++)
        o[obase + (long)(ty + 8 * i) * 2048 + tx] = __float2half(tile[tx][ty + 8 * i]);
}

__global__ void conv_h(const float* __restrict__ w, __half* __restrict__ h, int n)
{
    int i = blockIdx.x * 256 + threadIdx.x;
    if (i < n) h[i] = __float2half(w[i]);
}

__global__ void conv_8(const float* __restrict__ w, unsigned char* __restrict__ o,
                       float scale, int n)
{
    int i = blockIdx.x * 256 + threadIdx.x;
    if (i < n)
        o[i] = (unsigned char)__nv_cvt_float_to_fp8(w[i] * scale, __NV_SATFINITE, __NV_E4M3);
}

// fp8 transpose [c][n] -> [n][c] per batch (32x32 tiles)
__global__ void tr8(const unsigned char* __restrict__ in, unsigned char* __restrict__ o)
{
    __shared__ unsigned char tile[32][33];
    const int b = blockIdx.z;
    const int c0 = blockIdx.y * 32, n0 = blockIdx.x * 32;
    const int tx = threadIdx.x, ty = threadIdx.y;       // (32, 8)
    const long ib = (long)b * ELEMS;
#pragma unroll
    for (int i = 0; i < 4; i++)
        tile[ty + 8 * i][tx] = in[ib + (long)(c0 + ty + 8 * i) * 1024 + n0 + tx];
    __syncthreads();
#pragma unroll
    for (int i = 0; i < 4; i++)
        o[ib + (long)(n0 + ty + 8 * i) * 1024 + c0 + tx] = tile[tx][ty + 8 * i];
}

// ---------------------------------------------------------------------------
// softmaxes -> fp8 (x256)
// ---------------------------------------------------------------------------
__global__ void row_softmax_8(const float* __restrict__ in, unsigned char* __restrict__ oh)
{
    const long rowb = (long)blockIdx.x * 1024;
    const float4* p = (const float4*)(in + rowb);
    const int t = threadIdx.x;            // 256 threads x 4

    float4 v = p[t];
    float m = fmaxf(fmaxf(v.x, v.y), fmaxf(v.z, v.w));
    __shared__ float red[256];
    red[t] = m; __syncthreads();
    for (int s = 128; s > 0; s >>= 1) { if (t < s) red[t] = fmaxf(red[t], red[t + s]); __syncthreads(); }
    m = red[0]; __syncthreads();

    float e0 = __expf(v.x - m), e1 = __expf(v.y - m);
    float e2 = __expf(v.z - m), e3 = __expf(v.w - m);
    red[t] = e0 + e1 + e2 + e3; __syncthreads();
    for (int s = 128; s > 0; s >>= 1) { if (t < s) red[t] += red[t + s]; __syncthreads(); }
    const float inv = 256.0f / red[0];

    uint32_t lo = fp8x2(e0 * inv, e1 * inv);
    uint32_t hi = fp8x2(e2 * inv, e3 * inv);
    *(uint32_t*)(oh + rowb + t * 4) = lo | (hi << 16);
}

__global__ void col_softmax_8(const float* __restrict__ in, unsigned char* __restrict__ oh)
{
    const int b = blockIdx.y;
    const int tx = threadIdx.x, ty = threadIdx.y;       // (32, 8)
    const int n = blockIdx.x * 32 + tx;
    const long base = (long)b * ELEMS + n;

    __shared__ float red[8][32];

    float m = -1e30f;
    for (int c = ty; c < 1024; c += 8) m = fmaxf(m, in[base + ((long)c << 10)]);
    red[ty][tx] = m; __syncthreads();
    m = -1e30f;
#pragma unroll
    for (int j = 0; j < 8; j++) m = fmaxf(m, red[j][tx]);
    __syncthreads();

    float s = 0.0f;
    for (int c = ty; c < 1024; c += 8) s += __expf(in[base + ((long)c << 10)] - m);
    red[ty][tx] = s; __syncthreads();
    s = 0.0f;
#pragma unroll
    for (int j = 0; j < 8; j++) s += red[j][tx];
    const float inv = 256.0f / s;

    for (int c = ty; c < 1024; c += 8) {
        long idx = base + ((long)c << 10);
        oh[idx] = (unsigned char)__nv_cvt_float_to_fp8(
            __expf(in[idx] - m) * inv, __NV_SATFINITE, __NV_E4M3);
    }
}

// ---------------------------------------------------------------------------
// launch
// ---------------------------------------------------------------------------
#define SMEM_DYN (3 * 49152 + 1024)

extern "C" void kernel_launch(void* const* d_in, const int* in_sizes, int n_in,
                              void* d_out, int out_size)
{
    (void)in_sizes; (void)n_in; (void)out_size;

    const float* x  = (const float*)d_in[0];
    const float* wr = (const float*)d_in[1];
    const float* br = (const float*)d_in[2];
    const float* wc = (const float*)d_in[3];
    const float* bc = (const float*)d_in[4];
    const float* wd = (const float*)d_in[5];
    const float* bd = (const float*)d_in[6];
    float* out = (float*)d_out;

    float *y1, *cbuf, *dbuf;
    __half *xT, *wrh;
    unsigned char *y1s8, *y1s8T, *ch8, *dh8, *wc8, *wd8;
    cudaGetSymbolAddress((void**)&y1,    g_Y1);
    cudaGetSymbolAddress((void**)&cbuf,  g_C);
    cudaGetSymbolAddress((void**)&dbuf,  g_D);
    cudaGetSymbolAddress((void**)&xT,    g_XT);
    cudaGetSymbolAddress((void**)&y1s8,  g_Y1s8);
    cudaGetSymbolAddress((void**)&y1s8T, g_Y1s8T);
    cudaGetSymbolAddress((void**)&ch8,   g_Ch8);
    cudaGetSymbolAddress((void**)&dh8,   g_Dh8);
    cudaGetSymbolAddress((void**)&wrh,   g_Wr);
    cudaGetSymbolAddress((void**)&wc8,   g_Wc8);
    cudaGetSymbolAddress((void**)&wd8,   g_Wd8);

    cudaFuncSetAttribute((const void*)gemm_mma<0, 0>, cudaFuncAttributeMaxDynamicSharedMemorySize, SMEM_DYN);
    cudaFuncSetAttribute((const void*)gemm_mma<1, 1>, cudaFuncAttributeMaxDynamicSharedMemorySize, SMEM_DYN);
    cudaFuncSetAttribute((const void*)gemm_mma<1, 2>, cudaFuncAttributeMaxDynamicSharedMemorySize, SMEM_DYN);

    // conversions
    conv_h<<<(2 * 1024 * 1024) / 256, 256>>>(wr, wrh, 2 * 1024 * 1024);
    conv_8<<<(1024 * 1024) / 256, 256>>>(wc, wc8, 16.0f, 1024 * 1024);
    conv_8<<<(1024 * 1024) / 256, 256>>>(wd, wd8, 16.0f, 1024 * 1024);
    conv_x_T<<<dim3(32, 64, NB), dim3(32, 8)>>>(x, xT);

    dim3 g(4, 8, NB), blk(256);

    // GEMM1 (fp16): Y1 = Wr @ X + br ; writes fp32 Y1 + fp8(Y1*2) [c][n]
    gemm_mma<0, 0><<<g, blk, SMEM_DYN>>>(
        (const char*)wrh, 0L, (const char*)xT, (long)1024 * 2048 * 2, 4096,
        br, 1.0f, y1, nullptr, y1s8);

    // transpose fp8 Y1 -> [n][c] for GEMM2/3 B operand
    tr8<<<dim3(32, 32, NB), dim3(32, 8)>>>(y1s8, y1s8T);

    // GEMM2 (fp8): logits C = (Wc*16)@(Y1*2)^T / 32 + bc
    gemm_mma<1, 1><<<g, blk, SMEM_DYN>>>(
        (const char*)wc8, 0L, (const char*)y1s8T, (long)ELEMS, 1024,
        bc, 1.0f / 32.0f, cbuf, nullptr, nullptr);
    // GEMM3 (fp8): logits D
    gemm_mma<1, 1><<<g, blk, SMEM_DYN>>>(
        (const char*)wd8, 0L, (const char*)y1s8T, (long)ELEMS, 1024,
        bd, 1.0f / 32.0f, dbuf, nullptr, nullptr);

    row_softmax_8<<<NB * 1024, 256>>>(cbuf, ch8);
    col_softmax_8<<<dim3(32, NB), dim3(32, 8)>>>(dbuf, dh8);

    // GEMM4 (fp8): out = Y1 + (C*256)@(D*256)^T / 65536
    gemm_mma<1, 2><<<g, blk, SMEM_DYN>>>(
        (const char*)ch8, (long)ELEMS, (const char*)dh8, (long)ELEMS, 1024,
        nullptr, 1.0f / 65536.0f, out, y1, nullptr);
}

// round 12
// speedup vs baseline: 1.0896x; 1.0896x over previous
#include <cuda_runtime.h>
#include <cuda_fp16.h>
#include <cstdint>

// ---------------------------------------------------------------------------
// PSAttention (B=32, CIN=2048, COUT=HW=1024), all-fp16 mma.sync (HMMA.16816).
//   Y1 = Wr @ X + br                  (fp16 operands, fp32 accum, fp16 out)
//   [C;D] = [Wc;Wd] @ Y1 + [bc;bd]    (stacked M=2048 GEMM, fp16 logits)
//   C <- softmax_rows, D <- softmax_cols (fp16)
//   out = Y1 + C @ D^T                (fp32 out, fp16 addend)
// ---------------------------------------------------------------------------

#define NB 32
#define ELEMS (1024 * 1024)

__device__ __half  g_XT  [NB * 1024 * 2048];   // X^T fp16 (B for GEMM1)
__device__ __half  g_Y1h [NB * ELEMS];         // Y1 fp16 [c][n]
__device__ __half  g_Y1hT[NB * ELEMS];         // Y1^T fp16 [n][c]
__device__ __half  g_L   [NB * 2 * ELEMS];     // stacked logits [b][2048][1024]
__device__ __half  g_Ch  [NB * ELEMS];         // softmax C
__device__ __half  g_Dh  [NB * ELEMS];         // softmax D
__device__ __half  g_Wr  [1024 * 2048];
__device__ __half  g_Wcd [2 * ELEMS];          // [Wc; Wd]
__device__ float   g_Bcd [2048];               // [bc; bd]

// ---------------------------------------------------------------------------
// helpers
// ---------------------------------------------------------------------------
__device__ __forceinline__ uint32_t smem_u32(const void* p) {
    uint32_t a;
    asm("{ .reg .u64 t; cvta.to.shared.u64 t, %1; cvt.u32.u64 %0, t; }" : "=r"(a) : "l"(p));
    return a;
}
#define CP16(dst, src) \
    asm volatile("cp.async.cg.shared.global [%0], [%1], 16;" :: "r"(dst), "l"(src))

__device__ __forceinline__ uint32_t swz(uint32_t off) {
    return off ^ ((off >> 3) & 0x70);
}
__device__ __forceinline__ void ldsm4(uint32_t* r, uint32_t a) {
    asm volatile("ldmatrix.sync.aligned.m8n8.x4.shared.b16 {%0,%1,%2,%3}, [%4];"
        : "=r"(r[0]), "=r"(r[1]), "=r"(r[2]), "=r"(r[3]) : "r"(a));
}
__device__ __forceinline__ void mma16816(float* c, const uint32_t* a, const uint32_t* b) {
    asm volatile("mma.sync.aligned.m16n8k16.row.col.f32.f16.f16.f32 "
        "{%0,%1,%2,%3},{%4,%5,%6,%7},{%8,%9},{%0,%1,%2,%3};"
        : "+f"(c[0]), "+f"(c[1]), "+f"(c[2]), "+f"(c[3])
        : "r"(a[0]), "r"(a[1]), "r"(a[2]), "r"(a[3]), "r"(b[0]), "r"(b[1]));
}

// ---------------------------------------------------------------------------
// stage loader: A[128 x 64] + B[256 x 64] fp16 K-major, SW128.
// ---------------------------------------------------------------------------
#define STAGE 49152u
__device__ __forceinline__ void load_stage(
    uint32_t sb, int s, int m0, int n0, int K, int ks0,
    const __half* A, const __half* B, int tid)
{
    uint32_t buf = sb + (uint32_t)(s % 3) * STAGE;
#pragma unroll
    for (int i = 0; i < 4; i++) {
        int idx = tid + (i << 8);
        int r = idx >> 3, c = idx & 7;
        uint32_t sw = swz((uint32_t)(r * 128 + c * 16));
        CP16(buf + sw, A + (long)(m0 + r) * K + ks0 + (c << 3));
    }
#pragma unroll
    for (int i = 0; i < 8; i++) {
        int idx = tid + (i << 8);
        int r = idx >> 3, c = idx & 7;
        uint32_t sw = swz((uint32_t)(r * 128 + c * 16));
        CP16(buf + 16384u + sw, B + (long)(n0 + r) * K + ks0 + (c << 3));
    }
    asm volatile("cp.async.commit_group;" ::: "memory");
}

// ---------------------------------------------------------------------------
// GEMM: out[M,1024] per batch = A[M,K] * B[1024,K]^T (K-major fp16 operands).
// MODE 0: +bias[r], write fp16 outH (natural, batch stride obatch)
// MODE 2: +fp16 addend, write fp32 outF
// CTA 128x256, 8 warps = 2(m) x 4(n), warp tile 64x64. 3-stage cp.async,
// next-stage loads issued BEFORE the MMA loop (overlap loads with MMA).
// ---------------------------------------------------------------------------
template<int MODE>
__global__ __launch_bounds__(256, 1)
void gemm_mma(const __half* __restrict__ A_, long strideA,
              const __half* __restrict__ B_, long strideB, int K,
              const float* __restrict__ bias,
              __half* __restrict__ outH, long obatch,
              const __half* __restrict__ addH,
              float* __restrict__ outF)
{
    extern __shared__ char smraw[];
    uint32_t sb = (smem_u32(smraw) + 1023u) & ~1023u;
    const int tid = threadIdx.x, lane = tid & 31, wid = tid >> 5;
    const int bz = blockIdx.z;
    const int m0 = blockIdx.y * 128, n0 = blockIdx.x * 256;

    const __half* A = A_ + (long)bz * strideA;
    const __half* B = B_ + (long)bz * strideB;

    const int wm0 = (wid & 1) * 64;
    const int wn0 = (wid >> 1) * 64;

    float acc[4][8][4];
#pragma unroll
    for (int a = 0; a < 4; a++)
#pragma unroll
        for (int b = 0; b < 8; b++)
#pragma unroll
            for (int c = 0; c < 4; c++) acc[a][b][c] = 0.0f;

    const int nC = K >> 6;
    load_stage(sb, 0, m0, n0, K, 0,  A, B, tid);
    load_stage(sb, 1, m0, n0, K, 64, A, B, tid);

    const int      arow = wm0 + (lane & 15);
    const uint32_t akb0 = (uint32_t)((lane >> 4) * 16);
    const int      brow = wn0 + (lane & 7) + ((lane >> 4) << 3);
    const uint32_t bkb0 = (uint32_t)(((lane >> 3) & 1) * 16);

    for (int s = 0; s < nC; s++) {
        if (s == nC - 1) asm volatile("cp.async.wait_group 0;" ::: "memory");
        else             asm volatile("cp.async.wait_group 1;" ::: "memory");
        __syncthreads();

        // issue next-stage loads first so they overlap with the MMA work
        if (s + 2 < nC)
            load_stage(sb, s + 2, m0, n0, K, (s + 2) << 6, A, B, tid);

        uint32_t aB = sb + (uint32_t)(s % 3) * STAGE;
        uint32_t bB = aB + 16384u;

#pragma unroll
        for (int ks = 0; ks < 4; ks++) {
            uint32_t ah[4][4], bb[4][4];
            const uint32_t akb = (uint32_t)(ks * 32) + akb0;
            const uint32_t bkb = (uint32_t)(ks * 32) + bkb0;
#pragma unroll
            for (int mt = 0; mt < 4; mt++)
                ldsm4(ah[mt], aB + swz((uint32_t)((arow + mt * 16) * 128) + akb));
#pragma unroll
            for (int q = 0; q < 4; q++)
                ldsm4(bb[q], bB + swz((uint32_t)((brow + q * 16) * 128) + bkb));
#pragma unroll
            for (int mt = 0; mt < 4; mt++)
#pragma unroll
                for (int nb = 0; nb < 8; nb++)
                    mma16816(acc[mt][nb], ah[mt], &bb[nb >> 1][(nb & 1) * 2]);
        }
    }

    // ---- epilogue ----------------------------------------------------------
#pragma unroll
    for (int mt = 0; mt < 4; mt++) {
        const int r0 = m0 + wm0 + mt * 16 + (lane >> 2);
        float b0 = 0.0f, b1 = 0.0f;
        if (MODE == 0) { b0 = __ldg(&bias[r0]); b1 = __ldg(&bias[r0 + 8]); }
#pragma unroll
        for (int nb = 0; nb < 8; nb++) {
            const int col = n0 + wn0 + nb * 8 + (lane & 3) * 2;
            if (MODE == 0) {
                const long ob = (long)bz * obatch;
                float v0 = acc[mt][nb][0] + b0, v1 = acc[mt][nb][1] + b0;
                float v2 = acc[mt][nb][2] + b1, v3 = acc[mt][nb][3] + b1;
                *(__half2*)(outH + ob + (long)r0 * 1024 + col) = __floats2half2_rn(v0, v1);
                *(__half2*)(outH + ob + (long)(r0 + 8) * 1024 + col) = __floats2half2_rn(v2, v3);
            } else {
                const long ob = (long)bz << 20;
                const long i0 = ob + (long)r0 * 1024 + col;
                const long i1 = ob + (long)(r0 + 8) * 1024 + col;
                __half2 a0 = *(const __half2*)(addH + i0);
                __half2 a1 = *(const __half2*)(addH + i1);
                float v0 = acc[mt][nb][0] + __low2float(a0);
                float v1 = acc[mt][nb][1] + __high2float(a0);
                float v2 = acc[mt][nb][2] + __low2float(a1);
                float v3 = acc[mt][nb][3] + __high2float(a1);
                *(float2*)(outF + i0) = make_float2(v0, v1);
                *(float2*)(outF + i1) = make_float2(v2, v3);
            }
        }
    }
}

// ---------------------------------------------------------------------------
// conversions
// ---------------------------------------------------------------------------
// X [b][c=2048][n=1024] fp32 -> XT [b][n][c] fp16, 64c x 32n tiles
__global__ void conv_x_T(const float* __restrict__ X, __half* __restrict__ o)
{
    __shared__ float tile[64][33];
    const int b = blockIdx.z;
    const int c0 = blockIdx.y * 64, n0 = blockIdx.x * 32;
    const int tx = threadIdx.x, ty = threadIdx.y;      // (32, 8)
    const float* src = X + ((long)b * 2048 + c0) * 1024 + n0;
#pragma unroll
    for (int i = 0; i < 8; i++)
        tile[ty + 8 * i][tx] = src[(long)(ty + 8 * i) * 1024 + tx];
    __syncthreads();
    const long obase = ((long)b * 1024 + n0) * 2048 + c0;
#pragma unroll
    for (int i = 0; i < 4; i++) {
        int n = ty + 8 * i;
        __half2 v = __floats2half2_rn(tile[2 * tx][n], tile[2 * tx + 1][n]);
        *(__half2*)(o + obase + (long)n * 2048 + 2 * tx) = v;
    }
}

// fp16 transpose [c][n] -> [n][c] per batch, 64x64 tiles
__global__ void tr16(const __half* __restrict__ in, __half* __restrict__ o)
{
    __shared__ __half tile[64][66];
    const int b = blockIdx.z;
    const int c0 = blockIdx.y * 64, n0 = blockIdx.x * 64;
    const int lane = threadIdx.x & 31, w = threadIdx.x >> 5;   // 256 thr
    const __half* src = in + (long)b * ELEMS;
    __half* dst = o + (long)b * ELEMS;
#pragma unroll
    for (int i = 0; i < 8; i++) {
        int c = w + 8 * i;
        *(__half2*)&tile[c][lane * 2] =
            *(const __half2*)(src + (long)(c0 + c) * 1024 + n0 + lane * 2);
    }
    __syncthreads();
#pragma unroll
    for (int i = 0; i < 8; i++) {
        int n = w + 8 * i;
        __half2 v;
        v.x = tile[lane * 2][n];
        v.y = tile[lane * 2 + 1][n];
        *(__half2*)(dst + (long)(n0 + n) * 1024 + c0 + lane * 2) = v;
    }
}

__global__ void conv_h(const float* __restrict__ w, __half* __restrict__ h, int n)
{
    int i = blockIdx.x * 256 + threadIdx.x;
    if (i < n) h[i] = __float2half(w[i]);
}
__global__ void concat_bias(const float* __restrict__ bc, const float* __restrict__ bd,
                            float* __restrict__ o)
{
    int i = blockIdx.x * 256 + threadIdx.x;
    if (i < 1024) o[i] = bc[i];
    else if (i < 2048) o[i] = bd[i - 1024];
}

// ---------------------------------------------------------------------------
// softmaxes (fp16 logits in, fp16 out)
// ---------------------------------------------------------------------------
// rows: logits at [b*2048 + c][1024] -> Ch [b*1024 + c][1024]
__global__ void row_softmax_h(const __half* __restrict__ L, __half* __restrict__ oh)
{
    const int b = blockIdx.x >> 10, c = blockIdx.x & 1023;
    const __half2* row = (const __half2*)(L + ((long)b * 2048 + c) * 1024);
    __half2* orow = (__half2*)(oh + ((long)b * 1024 + c) * 1024);
    const int t = threadIdx.x;          // 256 threads x 4 halves

    __half2 h0 = row[t * 2], h1 = row[t * 2 + 1];
    float v0 = __low2float(h0), v1 = __high2float(h0);
    float v2 = __low2float(h1), v3 = __high2float(h1);
    float m = fmaxf(fmaxf(v0, v1), fmaxf(v2, v3));

    __shared__ float red[256];
    red[t] = m; __syncthreads();
    for (int s = 128; s > 0; s >>= 1) { if (t < s) red[t] = fmaxf(red[t], red[t + s]); __syncthreads(); }
    m = red[0]; __syncthreads();

    float e0 = __expf(v0 - m), e1 = __expf(v1 - m);
    float e2 = __expf(v2 - m), e3 = __expf(v3 - m);
    red[t] = e0 + e1 + e2 + e3; __syncthreads();
    for (int s = 128; s > 0; s >>= 1) { if (t < s) red[t] += red[t + s]; __syncthreads(); }
    const float inv = 1.0f / red[0];

    orow[t * 2]     = __floats2half2_rn(e0 * inv, e1 * inv);
    orow[t * 2 + 1] = __floats2half2_rn(e2 * inv, e3 * inv);
}

// cols: logits D at [b*2048 + 1024 + c][1024], softmax over c. Register-resident:
// block (32 n, 32 warps), each thread holds 32 values -> 1 read + 1 write.
__global__ void col_softmax_h(const __half* __restrict__ L, __half* __restrict__ oh)
{
    const int b = blockIdx.y;
    const int tx = threadIdx.x, ty = threadIdx.y;   // (32, 32)
    const int n = blockIdx.x * 32 + tx;
    const __half* basep = L + ((long)b * 2048 + 1024) * 1024 + n;
    __half* outp = oh + (long)b * ELEMS + n;

    __half vals[32];
#pragma unroll
    for (int i = 0; i < 32; i++)
        vals[i] = basep[(long)(ty + 32 * i) * 1024];

    float m = -1e30f;
#pragma unroll
    for (int i = 0; i < 32; i++) m = fmaxf(m, __half2float(vals[i]));

    __shared__ float red[32][33];
    red[ty][tx] = m; __syncthreads();
    m = -1e30f;
#pragma unroll
    for (int j = 0; j < 32; j++) m = fmaxf(m, red[j][tx]);
    __syncthreads();

    float e[32], s = 0.0f;
#pragma unroll
    for (int i = 0; i < 32; i++) { e[i] = __expf(__half2float(vals[i]) - m); s += e[i]; }
    red[ty][tx] = s; __syncthreads();
    s = 0.0f;
#pragma unroll
    for (int j = 0; j < 32; j++) s += red[j][tx];
    const float inv = 1.0f / s;

#pragma unroll
    for (int i = 0; i < 32; i++)
        outp[(long)(ty + 32 * i) * 1024] = __float2half(e[i] * inv);
}

// ---------------------------------------------------------------------------
// launch
// ---------------------------------------------------------------------------
#define SMEM_DYN (3 * 49152 + 1024)

extern "C" void kernel_launch(void* const* d_in, const int* in_sizes, int n_in,
                              void* d_out, int out_size)
{
    (void)in_sizes; (void)n_in; (void)out_size;

    const float* x  = (const float*)d_in[0];
    const float* wr = (const float*)d_in[1];
    const float* br = (const float*)d_in[2];
    const float* wc = (const float*)d_in[3];
    const float* bc = (const float*)d_in[4];
    const float* wd = (const float*)d_in[5];
    const float* bd = (const float*)d_in[6];
    float* out = (float*)d_out;

    __half *xT, *y1h, *y1hT, *lg, *ch, *dh, *wrh, *wcd;
    float* bcd;
    cudaGetSymbolAddress((void**)&xT,   g_XT);
    cudaGetSymbolAddress((void**)&y1h,  g_Y1h);
    cudaGetSymbolAddress((void**)&y1hT, g_Y1hT);
    cudaGetSymbolAddress((void**)&lg,   g_L);
    cudaGetSymbolAddress((void**)&ch,   g_Ch);
    cudaGetSymbolAddress((void**)&dh,   g_Dh);
    cudaGetSymbolAddress((void**)&wrh,  g_Wr);
    cudaGetSymbolAddress((void**)&wcd,  g_Wcd);
    cudaGetSymbolAddress((void**)&bcd,  g_Bcd);

    cudaFuncSetAttribute((const void*)gemm_mma<0>, cudaFuncAttributeMaxDynamicSharedMemorySize, SMEM_DYN);
    cudaFuncSetAttribute((const void*)gemm_mma<2>, cudaFuncAttributeMaxDynamicSharedMemorySize, SMEM_DYN);

    // conversions
    conv_h<<<(2 * 1024 * 1024) / 256, 256>>>(wr, wrh, 2 * 1024 * 1024);
    conv_h<<<(1024 * 1024) / 256, 256>>>(wc, wcd, 1024 * 1024);
    conv_h<<<(1024 * 1024) / 256, 256>>>(wd, wcd + ELEMS, 1024 * 1024);
    concat_bias<<<8, 256>>>(bc, bd, bcd);
    conv_x_T<<<dim3(32, 32, NB), dim3(32, 8)>>>(x, xT);

    // GEMM1: Y1 = Wr @ X + br -> fp16 [c][n]
    gemm_mma<0><<<dim3(4, 8, NB), 256, SMEM_DYN>>>(
        wrh, 0L, xT, (long)1024 * 2048, 2048, br, y1h, (long)ELEMS, nullptr, nullptr);

    // Y1^T for GEMM2/3 B operand
    tr16<<<dim3(16, 16, NB), 256>>>(y1h, y1hT);

    // stacked GEMM2+3: [C;D] = [Wc;Wd] @ Y1 + [bc;bd] -> fp16 logits [2048][1024]
    gemm_mma<0><<<dim3(4, 16, NB), 256, SMEM_DYN>>>(
        wcd, 0L, y1hT, (long)ELEMS, 1024, bcd, lg, (long)2 * ELEMS, nullptr, nullptr);

    row_softmax_h<<<NB * 1024, 256>>>(lg, ch);
    col_softmax_h<<<dim3(32, NB), dim3(32, 32)>>>(lg, dh);

    // GEMM4: out = Y1 + C @ D^T (fp32 out, fp16 addend)
    gemm_mma<2><<<dim3(4, 8, NB), 256, SMEM_DYN>>>(
        ch, (long)ELEMS, dh, (long)ELEMS, 1024, nullptr, nullptr, 0L, y1h, out);
}

// round 13
// speedup vs baseline: 1.1063x; 1.0153x over previous
#include <cuda_runtime.h>
#include <cuda_fp16.h>
#include <cstdint>

// ---------------------------------------------------------------------------
// PSAttention (B=32, CIN=2048, COUT=HW=1024), all-fp16 mma.sync (HMMA.16816).
//   Y1 = Wr @ X + br                  (B = X [c][n] natural, ldmatrix.trans)
//   [C;D] = [Wc;Wd] @ Y1 + [bc;bd]    (B = Y1 [c][n] natural, ldmatrix.trans)
//   C <- softmax_rows, D <- softmax_cols
//   out = Y1 + C @ D^T                (B = D [d][n'] K-major, normal path)
// No explicit transposes anywhere.
// ---------------------------------------------------------------------------

#define NB 32
#define ELEMS (1024 * 1024)

__device__ __half  g_Xh  [NB * 2048 * 1024];   // X fp16, same layout as input
__device__ __half  g_Y1h [NB * ELEMS];         // Y1 fp16 [c][n]
__device__ __half  g_L   [NB * 2 * ELEMS];     // stacked logits [b][2048][1024]
__device__ __half  g_Ch  [NB * ELEMS];         // softmax C
__device__ __half  g_Dh  [NB * ELEMS];         // softmax D
__device__ __half  g_Wr  [1024 * 2048];
__device__ __half  g_Wcd [2 * ELEMS];          // [Wc; Wd]
__device__ float   g_Bcd [2048];               // [bc; bd]

// ---------------------------------------------------------------------------
// helpers
// ---------------------------------------------------------------------------
__device__ __forceinline__ uint32_t smem_u32(const void* p) {
    uint32_t a;
    asm("{ .reg .u64 t; cvta.to.shared.u64 t, %1; cvt.u32.u64 %0, t; }" : "=r"(a) : "l"(p));
    return a;
}
#define CP16(dst, src) \
    asm volatile("cp.async.cg.shared.global [%0], [%1], 16;" :: "r"(dst), "l"(src))

__device__ __forceinline__ uint32_t swz(uint32_t off) {       // SW128 (A tiles)
    return off ^ ((off >> 3) & 0x70);
}
__device__ __forceinline__ void ldsm4(uint32_t* r, uint32_t a) {
    asm volatile("ldmatrix.sync.aligned.m8n8.x4.shared.b16 {%0,%1,%2,%3}, [%4];"
        : "=r"(r[0]), "=r"(r[1]), "=r"(r[2]), "=r"(r[3]) : "r"(a));
}
__device__ __forceinline__ void ldsm4t(uint32_t* r, uint32_t a) {
    asm volatile("ldmatrix.sync.aligned.m8n8.x4.trans.shared.b16 {%0,%1,%2,%3}, [%4];"
        : "=r"(r[0]), "=r"(r[1]), "=r"(r[2]), "=r"(r[3]) : "r"(a));
}
__device__ __forceinline__ void mma16816(float* c, const uint32_t* a, const uint32_t* b) {
    asm volatile("mma.sync.aligned.m16n8k16.row.col.f32.f16.f16.f32 "
        "{%0,%1,%2,%3},{%4,%5,%6,%7},{%8,%9},{%0,%1,%2,%3};"
        : "+f"(c[0]), "+f"(c[1]), "+f"(c[2]), "+f"(c[3])
        : "r"(a[0]), "r"(a[1]), "r"(a[2]), "r"(a[3]), "r"(b[0]), "r"(b[1]));
}

// ---------------------------------------------------------------------------
// stage loaders. Stage = 48KB: A [128 rows x 128B, SW128] @ +0,
//   B @ +16384:
//     BTRANS=0: [256 n-rows x 128B K-major, SW128]
//     BTRANS=1: [64 k-rows x 512B n-contiguous, 16B-chunk XOR swizzle]
// ---------------------------------------------------------------------------
#define STAGE 49152u
template<int BTRANS>
__device__ __forceinline__ void load_stage(
    uint32_t sb, int s, int m0, int n0, int K, int ks0,
    const __half* A, const __half* B, int bStride, int tid)
{
    uint32_t buf = sb + (uint32_t)(s % 3) * STAGE;
#pragma unroll
    for (int i = 0; i < 4; i++) {          // A: 128 rows x 8 x 16B (K-major)
        int idx = tid + (i << 8);
        int r = idx >> 3, c = idx & 7;
        uint32_t sw = swz((uint32_t)(r * 128 + c * 16));
        CP16(buf + sw, A + (long)(m0 + r) * K + ks0 + (c << 3));
    }
    if (BTRANS) {
#pragma unroll
        for (int i = 0; i < 8; i++) {      // B: 64 k-rows x 32 x 16B chunks
            int idx = tid + (i << 8);
            int r = idx >> 5, c = idx & 31;
            uint32_t dst = buf + 16384u + (uint32_t)(r * 512 + ((c ^ (r & 7)) << 4));
            CP16(dst, B + (long)(ks0 + r) * bStride + n0 + (c << 3));
        }
    } else {
#pragma unroll
        for (int i = 0; i < 8; i++) {      // B: 256 n-rows x 8 x 16B (K-major)
            int idx = tid + (i << 8);
            int r = idx >> 3, c = idx & 7;
            uint32_t sw = swz((uint32_t)(r * 128 + c * 16));
            CP16(buf + 16384u + sw, B + (long)(n0 + r) * K + ks0 + (c << 3));
        }
    }
    asm volatile("cp.async.commit_group;" ::: "memory");
}

// ---------------------------------------------------------------------------
// GEMM: out[M,1024] per batch = A[M,K] @ B, fp16 operands, fp32 accum.
//   BTRANS=1: B given as [K][1024] natural (row stride bStride)
//   BTRANS=0: B given as [1024][K] K-major
// MODE 0: +bias[r], write fp16 outH (batch stride obatch)
// MODE 2: +fp16 addend, write fp32 outF
// CTA 128x256, 8 warps = 2(m) x 4(n), warp tile 64x64, 3-stage cp.async.
// ---------------------------------------------------------------------------
template<int BTRANS, int MODE>
__global__ __launch_bounds__(256, 1)
void gemm_mma(const __half* __restrict__ A_, long strideA,
              const __half* __restrict__ B_, long strideB, int bStride, int K,
              const float* __restrict__ bias,
              __half* __restrict__ outH, long obatch,
              const __half* __restrict__ addH,
              float* __restrict__ outF)
{
    extern __shared__ char smraw[];
    uint32_t sb = (smem_u32(smraw) + 1023u) & ~1023u;
    const int tid = threadIdx.x, lane = tid & 31, wid = tid >> 5;
    const int bz = blockIdx.z;
    const int m0 = blockIdx.y * 128, n0 = blockIdx.x * 256;

    const __half* A = A_ + (long)bz * strideA;
    const __half* B = B_ + (long)bz * strideB;

    const int wm0 = (wid & 1) * 64;
    const int wn0 = (wid >> 1) * 64;

    float acc[4][8][4];
#pragma unroll
    for (int a = 0; a < 4; a++)
#pragma unroll
        for (int b = 0; b < 8; b++)
#pragma unroll
            for (int c = 0; c < 4; c++) acc[a][b][c] = 0.0f;

    const int nC = K >> 6;
    load_stage<BTRANS>(sb, 0, m0, n0, K, 0,  A, B, bStride, tid);
    load_stage<BTRANS>(sb, 1, m0, n0, K, 64, A, B, bStride, tid);

    // A ldmatrix lane constants (K-major, SW128)
    const int      arow = wm0 + (lane & 15);
    const uint32_t akb0 = (uint32_t)((lane >> 4) * 16);
    // B K-major lane constants
    const int      brow = wn0 + (lane & 7) + ((lane >> 4) << 3);
    const uint32_t bkb0 = (uint32_t)(((lane >> 3) & 1) * 16);
    // B trans lane constants: matrices (lane>>3): 0,1 -> n-chunk +0 (k 0-7 / 8-15),
    //                                             2,3 -> n-chunk +1
    const int      tkr  = ((lane >> 3) & 1) * 8 + (lane & 7);  // k row within k16
    const int      tnc0 = (wn0 >> 3) + (lane >> 4);            // base n chunk

    for (int s = 0; s < nC; s++) {
        if (s == nC - 1) asm volatile("cp.async.wait_group 0;" ::: "memory");
        else             asm volatile("cp.async.wait_group 1;" ::: "memory");
        __syncthreads();

        if (s + 2 < nC)
            load_stage<BTRANS>(sb, s + 2, m0, n0, K, (s + 2) << 6, A, B, bStride, tid);

        uint32_t aB = sb + (uint32_t)(s % 3) * STAGE;
        uint32_t bB = aB + 16384u;

#pragma unroll
        for (int ks = 0; ks < 4; ks++) {
            uint32_t ah[4][4], bb[4][4];
            const uint32_t akb = (uint32_t)(ks * 32) + akb0;
#pragma unroll
            for (int mt = 0; mt < 4; mt++)
                ldsm4(ah[mt], aB + swz((uint32_t)((arow + mt * 16) * 128) + akb));
            if (BTRANS) {
                const int kr = ks * 16 + tkr;
                const uint32_t rb = bB + (uint32_t)(kr * 512);
                const int sx = kr & 7;
#pragma unroll
                for (int q = 0; q < 4; q++)
                    ldsm4t(bb[q], rb + (uint32_t)(((tnc0 + 2 * q) ^ sx) << 4));
            } else {
                const uint32_t bkb = (uint32_t)(ks * 32) + bkb0;
#pragma unroll
                for (int q = 0; q < 4; q++)
                    ldsm4(bb[q], bB + swz((uint32_t)((brow + q * 16) * 128) + bkb));
            }
#pragma unroll
            for (int mt = 0; mt < 4; mt++)
#pragma unroll
                for (int nb = 0; nb < 8; nb++)
                    mma16816(acc[mt][nb], ah[mt], &bb[nb >> 1][(nb & 1) * 2]);
        }
    }

    // ---- epilogue ----------------------------------------------------------
#pragma unroll
    for (int mt = 0; mt < 4; mt++) {
        const int r0 = m0 + wm0 + mt * 16 + (lane >> 2);
        float b0 = 0.0f, b1 = 0.0f;
        if (MODE == 0) { b0 = __ldg(&bias[r0]); b1 = __ldg(&bias[r0 + 8]); }
#pragma unroll
        for (int nb = 0; nb < 8; nb++) {
            const int col = n0 + wn0 + nb * 8 + (lane & 3) * 2;
            if (MODE == 0) {
                const long ob = (long)bz * obatch;
                float v0 = acc[mt][nb][0] + b0, v1 = acc[mt][nb][1] + b0;
                float v2 = acc[mt][nb][2] + b1, v3 = acc[mt][nb][3] + b1;
                *(__half2*)(outH + ob + (long)r0 * 1024 + col) = __floats2half2_rn(v0, v1);
                *(__half2*)(outH + ob + (long)(r0 + 8) * 1024 + col) = __floats2half2_rn(v2, v3);
            } else {
                const long ob = (long)bz << 20;
                const long i0 = ob + (long)r0 * 1024 + col;
                const long i1 = ob + (long)(r0 + 8) * 1024 + col;
                __half2 a0 = *(const __half2*)(addH + i0);
                __half2 a1 = *(const __half2*)(addH + i1);
                float v0 = acc[mt][nb][0] + __low2float(a0);
                float v1 = acc[mt][nb][1] + __high2float(a0);
                float v2 = acc[mt][nb][2] + __low2float(a1);
                float v3 = acc[mt][nb][3] + __high2float(a1);
                *(float2*)(outF + i0) = make_float2(v0, v1);
                *(float2*)(outF + i1) = make_float2(v2, v3);
            }
        }
    }
}

// ---------------------------------------------------------------------------
// conversions (all elementwise, fully coalesced)
// ---------------------------------------------------------------------------
// X fp32 -> fp16, same layout. 8 elements/thread.
__global__ void conv_x(const float4* __restrict__ X, uint4* __restrict__ o)
{
    long i = (long)blockIdx.x * 256 + threadIdx.x;
    float4 a = X[2 * i], b = X[2 * i + 1];
    __half2 h0 = __floats2half2_rn(a.x, a.y);
    __half2 h1 = __floats2half2_rn(a.z, a.w);
    __half2 h2 = __floats2half2_rn(b.x, b.y);
    __half2 h3 = __floats2half2_rn(b.z, b.w);
    uint4 v;
    v.x = *(uint32_t*)&h0; v.y = *(uint32_t*)&h1;
    v.z = *(uint32_t*)&h2; v.w = *(uint32_t*)&h3;
    o[i] = v;
}

__global__ void conv_h(const float* __restrict__ w, __half* __restrict__ h, int n)
{
    int i = blockIdx.x * 256 + threadIdx.x;
    if (i < n) h[i] = __float2half(w[i]);
}
__global__ void concat_bias(const float* __restrict__ bc, const float* __restrict__ bd,
                            float* __restrict__ o)
{
    int i = blockIdx.x * 256 + threadIdx.x;
    if (i < 1024) o[i] = bc[i];
    else if (i < 2048) o[i] = bd[i - 1024];
}

// ---------------------------------------------------------------------------
// softmaxes (fp16 logits in, fp16 out)
// ---------------------------------------------------------------------------
__global__ void row_softmax_h(const __half* __restrict__ L, __half* __restrict__ oh)
{
    const int b = blockIdx.x >> 10, c = blockIdx.x & 1023;
    const __half2* row = (const __half2*)(L + ((long)b * 2048 + c) * 1024);
    __half2* orow = (__half2*)(oh + ((long)b * 1024 + c) * 1024);
    const int t = threadIdx.x;            // 256 threads x 4 halves

    __half2 h0 = row[t * 2], h1 = row[t * 2 + 1];
    float v0 = __low2float(h0), v1 = __high2float(h0);
    float v2 = __low2float(h1), v3 = __high2float(h1);
    float m = fmaxf(fmaxf(v0, v1), fmaxf(v2, v3));

    __shared__ float red[256];
    red[t] = m; __syncthreads();
    for (int s = 128; s > 0; s >>= 1) { if (t < s) red[t] = fmaxf(red[t], red[t + s]); __syncthreads(); }
    m = red[0]; __syncthreads();

    float e0 = __expf(v0 - m), e1 = __expf(v1 - m);
    float e2 = __expf(v2 - m), e3 = __expf(v3 - m);
    red[t] = e0 + e1 + e2 + e3; __syncthreads();
    for (int s = 128; s > 0; s >>= 1) { if (t < s) red[t] += red[t + s]; __syncthreads(); }
    const float inv = 1.0f / red[0];

    orow[t * 2]     = __floats2half2_rn(e0 * inv, e1 * inv);
    orow[t * 2 + 1] = __floats2half2_rn(e2 * inv, e3 * inv);
}

__global__ void col_softmax_h(const __half* __restrict__ L, __half* __restrict__ oh)
{
    const int b = blockIdx.y;
    const int tx = threadIdx.x, ty = threadIdx.y;   // (32, 32)
    const int n = blockIdx.x * 32 + tx;
    const __half* basep = L + ((long)b * 2048 + 1024) * 1024 + n;
    __half* outp = oh + (long)b * ELEMS + n;

    __half vals[32];
#pragma unroll
    for (int i = 0; i < 32; i++)
        vals[i] = basep[(long)(ty + 32 * i) * 1024];

    float m = -1e30f;
#pragma unroll
    for (int i = 0; i < 32; i++) m = fmaxf(m, __half2float(vals[i]));

    __shared__ float red[32][33];
    red[ty][tx] = m; __syncthreads();
    m = -1e30f;
#pragma unroll
    for (int j = 0; j < 32; j++) m = fmaxf(m, red[j][tx]);
    __syncthreads();

    float e[32], s = 0.0f;
#pragma unroll
    for (int i = 0; i < 32; i++) { e[i] = __expf(__half2float(vals[i]) - m); s += e[i]; }
    red[ty][tx] = s; __syncthreads();
    s = 0.0f;
#pragma unroll
    for (int j = 0; j < 32; j++) s += red[j][tx];
    const float inv = 1.0f / s;

#pragma unroll
    for (int i = 0; i < 32; i++)
        outp[(long)(ty + 32 * i) * 1024] = __float2half(e[i] * inv);
}

// ---------------------------------------------------------------------------
// launch
// ---------------------------------------------------------------------------
#define SMEM_DYN (3 * 49152 + 1024)

extern "C" void kernel_launch(void* const* d_in, const int* in_sizes, int n_in,
                              void* d_out, int out_size)
{
    (void)in_sizes; (void)n_in; (void)out_size;

    const float* x  = (const float*)d_in[0];
    const float* wr = (const float*)d_in[1];
    const float* br = (const float*)d_in[2];
    const float* wc = (const float*)d_in[3];
    const float* bc = (const float*)d_in[4];
    const float* wd = (const float*)d_in[5];
    const float* bd = (const float*)d_in[6];
    float* out = (float*)d_out;

    __half *xh, *y1h, *lg, *ch, *dh, *wrh, *wcd;
    float* bcd;
    cudaGetSymbolAddress((void**)&xh,   g_Xh);
    cudaGetSymbolAddress((void**)&y1h,  g_Y1h);
    cudaGetSymbolAddress((void**)&lg,   g_L);
    cudaGetSymbolAddress((void**)&ch,   g_Ch);
    cudaGetSymbolAddress((void**)&dh,   g_Dh);
    cudaGetSymbolAddress((void**)&wrh,  g_Wr);
    cudaGetSymbolAddress((void**)&wcd,  g_Wcd);
    cudaGetSymbolAddress((void**)&bcd,  g_Bcd);

    cudaFuncSetAttribute((const void*)gemm_mma<1, 0>, cudaFuncAttributeMaxDynamicSharedMemorySize, SMEM_DYN);
    cudaFuncSetAttribute((const void*)gemm_mma<0, 2>, cudaFuncAttributeMaxDynamicSharedMemorySize, SMEM_DYN);

    // conversions
    conv_h<<<(2 * 1024 * 1024) / 256, 256>>>(wr, wrh, 2 * 1024 * 1024);
    conv_h<<<(1024 * 1024) / 256, 256>>>(wc, wcd, 1024 * 1024);
    conv_h<<<(1024 * 1024) / 256, 256>>>(wd, wcd + ELEMS, 1024 * 1024);
    concat_bias<<<8, 256>>>(bc, bd, bcd);
    conv_x<<<32768, 256>>>((const float4*)x, (uint4*)xh);   // 64M elems, 8/thread

    // GEMM1: Y1 = Wr @ X + br -> fp16 [c][n]  (B = Xh natural, trans path)
    gemm_mma<1, 0><<<dim3(4, 8, NB), 256, SMEM_DYN>>>(
        wrh, 0L, xh, (long)2048 * 1024, 1024, 2048, br, y1h, (long)ELEMS, nullptr, nullptr);

    // stacked GEMM2+3: [C;D] = [Wc;Wd] @ Y1 + [bc;bd]  (B = Y1h natural, trans path)
    gemm_mma<1, 0><<<dim3(4, 16, NB), 256, SMEM_DYN>>>(
        wcd, 0L, y1h, (long)ELEMS, 1024, 1024, bcd, lg, (long)2 * ELEMS, nullptr, nullptr);

    row_softmax_h<<<NB * 1024, 256>>>(lg, ch);
    col_softmax_h<<<dim3(32, NB), dim3(32, 32)>>>(lg, dh);

    // GEMM4: out = Y1 + C @ D^T  (B = Dh K-major, normal path)
    gemm_mma<0, 2><<<dim3(4, 8, NB), 256, SMEM_DYN>>>(
        ch, (long)ELEMS, dh, (long)ELEMS, 1024, 1024, nullptr, nullptr, 0L, y1h, out);
}